// round 16
// baseline (speedup 1.0000x reference)
#include <cuda_runtime.h>
#include <cuda_fp16.h>
#include <cstdint>

typedef __half f16;

#define S_ 1024
#define T_ 1024
#define B_ 32
#define D_ 1024
#define A_ 1024

// ---------------------------------------------------------------------------
// Scratch (device globals; allocation is forbidden)
// ---------------------------------------------------------------------------
__device__ __align__(16) f16  g_srcHi[(size_t)S_ * B_ * D_];   // (S,B,D) fp16 split
__device__ __align__(16) f16  g_srcLo[(size_t)S_ * B_ * D_];
__device__ __align__(16) f16  g_tgtHi[(size_t)T_ * B_ * D_];   // (T,B,D)
__device__ __align__(16) f16  g_tgtLo[(size_t)T_ * B_ * D_];
__device__ __align__(16) f16  g_mtHi[(size_t)A_ * D_];         // Mt[e,d]
__device__ __align__(16) f16  g_mtLo[(size_t)A_ * D_];
__device__ __align__(16) float g_mtPart[4][(size_t)A_ * D_];   // split-K partials
__device__ __align__(16) f16  g_uHi[(size_t)S_ * B_ * A_];     // (S,B,A)
__device__ __align__(16) f16  g_uLo[(size_t)S_ * B_ * A_];
__device__ __align__(16) float g_sc[(size_t)B_ * T_ * S_];     // (B,T,S) scores
__device__ __align__(16) f16  g_wF16[(size_t)B_ * T_ * S_];    // softmax weights fp16

// ---------------------------------------------------------------------------
// Primitives (sm_80-level PTX)
// ---------------------------------------------------------------------------
__device__ __forceinline__ uint32_t smem_u32(const void* p) {
    uint32_t a;
    asm("{ .reg .u64 t; cvta.to.shared.u64 t, %1; cvt.u32.u64 %0, t; }" : "=r"(a) : "l"(p));
    return a;
}

__device__ __forceinline__ void cpa16(uint32_t s, const void* g) {
    asm volatile("cp.async.cg.shared.global [%0], [%1], 16;" :: "r"(s), "l"(g));
}
#define CP_COMMIT() asm volatile("cp.async.commit_group;" ::: "memory")
#define CP_WAIT1()  asm volatile("cp.async.wait_group 1;" ::: "memory")

__device__ __forceinline__ void ldsm4(uint32_t* r, uint32_t a) {
    asm volatile("ldmatrix.sync.aligned.m8n8.x4.shared.b16 {%0,%1,%2,%3}, [%4];"
                 : "=r"(r[0]), "=r"(r[1]), "=r"(r[2]), "=r"(r[3]) : "r"(a));
}
__device__ __forceinline__ void ldsm4t(uint32_t* r, uint32_t a) {
    asm volatile("ldmatrix.sync.aligned.m8n8.x4.trans.shared.b16 {%0,%1,%2,%3}, [%4];"
                 : "=r"(r[0]), "=r"(r[1]), "=r"(r[2]), "=r"(r[3]) : "r"(a));
}
__device__ __forceinline__ void mma_f16(float* c, const uint32_t* a, const uint32_t* b) {
    asm volatile("mma.sync.aligned.m16n8k16.row.col.f32.f16.f16.f32 "
                 "{%0,%1,%2,%3}, {%4,%5,%6,%7}, {%8,%9}, {%0,%1,%2,%3};"
                 : "+f"(c[0]), "+f"(c[1]), "+f"(c[2]), "+f"(c[3])
                 : "r"(a[0]), "r"(a[1]), "r"(a[2]), "r"(a[3]), "r"(b[0]), "r"(b[1]));
}

__device__ __forceinline__ void f16split(float x, f16& h, f16& l) {
    h = __float2half_rn(x);
    l = __float2half_rn(x - __half2float(h));
}

// ---------------------------------------------------------------------------
// Tile loaders (XOR swizzle, no padding), 2B elements, 128-thread CTAs.
// NT tile: 128 rows x 64B (4 iters). TR tile: 32 rows x 256B (4 iters).
// ---------------------------------------------------------------------------
__device__ __forceinline__ void load_nt(uint32_t sbase, const void* g, long ldBytes, int tid) {
    #pragma unroll
    for (int i = 0; i < 4; i++) {
        const int c = tid + i * 128;
        const int row = c >> 2, ch = c & 3;
        const int sw = ch ^ ((row >> 1) & 3);
        cpa16(sbase + row * 64 + sw * 16, (const char*)g + (long)row * ldBytes + ch * 16);
    }
}
__device__ __forceinline__ void load_tr(uint32_t sbase, const void* g, long ldBytes, int tid) {
    #pragma unroll
    for (int i = 0; i < 4; i++) {
        const int c = tid + i * 128;
        const int row = c >> 4, ch = c & 15;
        const int sw = ch ^ (row & 7);
        cpa16(sbase + row * 256 + sw * 16, (const char*)g + (long)row * ldBytes + ch * 16);
    }
}

// ---------------------------------------------------------------------------
// fp16x3-split GEMM (GEMM4/5): C[m,n](z) = sum_k A[m,k]*B[n,k]  (NT)
// CTA 128x128x32, 4 warps (2x2 grid, 64x64 warp tiles), 128 threads,
// 3-stage ring, 2 CTAs/SM. Prefetch issued AFTER first MMA burst so the
// tensor pipe is fed immediately at chunk start.
// acc += Ahi*Bhi + Ahi*Blo + Alo*Bhi
// ---------------------------------------------------------------------------
#define HALF_B   8192           // one tile half: 128 x 64B
#define STAGE_B  32768
#define SM_TOTAL (3 * STAGE_B)  // 98304 per CTA

template <bool SPLITOUT>
__global__ __launch_bounds__(128, 2) void mma_gemm(
    const f16* __restrict__ Ah, const f16* __restrict__ Al,
    const f16* __restrict__ Bh, const f16* __restrict__ Bl,
    float* __restrict__ C, f16* __restrict__ Oh, f16* __restrict__ Ol,
    long lda, long ldb, long ldc, long aB, long bB, long cB)
{
    extern __shared__ char smem[];
    const uint32_t sb = smem_u32(smem);
    const int tid = threadIdx.x;
    const int lane = tid & 31, wid = tid >> 5;
    const int wy = wid >> 1, wx = wid & 1;        // 2x2 warps, 64x64 tiles
    const long m0 = (long)blockIdx.y * 128;
    const long n0 = (long)blockIdx.x * 128;
    const long z  = blockIdx.z;

    const f16* pAh = Ah + z * aB + m0 * lda;
    const f16* pAl = Al + z * aB + m0 * lda;
    const f16* pBh = Bh + z * bB + n0 * ldb;
    const f16* pBl = Bl + z * bB + n0 * ldb;

    float acc[4][8][4] = {};

    auto LOAD = [&](uint32_t st, int chunk) {
        const long k0 = (long)chunk * 32;
        load_nt(st,              pAh + k0, lda * 2, tid);
        load_nt(st + HALF_B,     pAl + k0, lda * 2, tid);
        load_nt(st + 2 * HALF_B, pBh + k0, ldb * 2, tid);
        load_nt(st + 3 * HALF_B, pBl + k0, ldb * 2, tid);
    };

    const int hi4 = lane >> 4;
    const uint32_t aRowB = (uint32_t)(wy * 64 + (lane & 15)) * 64;
    const int sA = ((lane & 15) >> 1) & 3;
    const uint32_t bRowB = (uint32_t)(wx * 64 + (lane & 7) + (hi4 << 3)) * 64;
    const int sB = (((lane & 7) + (hi4 << 3)) >> 1) & 3;
    const int bSel = (lane >> 3) & 1;

    LOAD(sb, 0); CP_COMMIT();
    LOAD(sb + STAGE_B, 1); CP_COMMIT();

    const uint32_t sEnd = sb + 3 * STAGE_B;
    uint32_t stCur = sb;
    uint32_t stLd  = sb + 2 * STAGE_B;

    const int NC = 32;
    for (int c = 0; c < NC; c++) {
        CP_WAIT1();
        __syncthreads();                  // visibility fence + stage-free point

        // ---- k16 = 0 fragment loads ----
        uint32_t bh[16], bl[16];
        {
            const uint32_t cOff = (uint32_t)(bSel ^ sB) * 16;
            #pragma unroll
            for (int p = 0; p < 4; p++) {
                const uint32_t bd = stCur + 2 * HALF_B + bRowB + (uint32_t)p * 16 * 64 + cOff;
                ldsm4(&bh[p * 4], bd);
                ldsm4(&bl[p * 4], bd + HALF_B);
            }
        }
        const uint32_t aOff0 = (uint32_t)(hi4 ^ sA) * 16;
        uint32_t ah0[4], al0[4];
        {
            const uint32_t ad = stCur + aRowB + aOff0;
            ldsm4(ah0, ad);
            ldsm4(al0, ad + HALF_B);
        }

        // ---- first MMA burst feeds the tensor pipe immediately ----
        #pragma unroll
        for (int nt = 0; nt < 8; nt++) {
            mma_f16(acc[0][nt], ah0, &bh[nt * 2]);
            mma_f16(acc[0][nt], ah0, &bl[nt * 2]);
            mma_f16(acc[0][nt], al0, &bh[nt * 2]);
        }

        // ---- prefetch chunk c+2 (issue hides under queued MMAs) ----
        if (c + 2 < NC) LOAD(stLd, c + 2);
        CP_COMMIT();

        #pragma unroll
        for (int mt = 1; mt < 4; mt++) {
            uint32_t ah[4], al[4];
            const uint32_t ad = stCur + aRowB + (uint32_t)mt * 16 * 64 + aOff0;
            ldsm4(ah, ad);
            ldsm4(al, ad + HALF_B);
            #pragma unroll
            for (int nt = 0; nt < 8; nt++) {
                mma_f16(acc[mt][nt], ah, &bh[nt * 2]);
                mma_f16(acc[mt][nt], ah, &bl[nt * 2]);
                mma_f16(acc[mt][nt], al, &bh[nt * 2]);
            }
        }

        // ---- k16 = 1 ----
        {
            const uint32_t cOff = (uint32_t)((2 + bSel) ^ sB) * 16;
            #pragma unroll
            for (int p = 0; p < 4; p++) {
                const uint32_t bd = stCur + 2 * HALF_B + bRowB + (uint32_t)p * 16 * 64 + cOff;
                ldsm4(&bh[p * 4], bd);
                ldsm4(&bl[p * 4], bd + HALF_B);
            }
        }
        const uint32_t aOff1 = (uint32_t)((2 + hi4) ^ sA) * 16;
        #pragma unroll
        for (int mt = 0; mt < 4; mt++) {
            uint32_t ah[4], al[4];
            const uint32_t ad = stCur + aRowB + (uint32_t)mt * 16 * 64 + aOff1;
            ldsm4(ah, ad);
            ldsm4(al, ad + HALF_B);
            #pragma unroll
            for (int nt = 0; nt < 8; nt++) {
                mma_f16(acc[mt][nt], ah, &bh[nt * 2]);
                mma_f16(acc[mt][nt], ah, &bl[nt * 2]);
                mma_f16(acc[mt][nt], al, &bh[nt * 2]);
            }
        }

        stCur += STAGE_B; if (stCur == sEnd) stCur = sb;
        stLd  += STAGE_B; if (stLd  == sEnd) stLd  = sb;
    }

    #pragma unroll
    for (int mt = 0; mt < 4; mt++) {
        #pragma unroll
        for (int half = 0; half < 2; half++) {
            const long row = m0 + wy * 64 + mt * 16 + (lane >> 2) + half * 8;
            #pragma unroll
            for (int nt = 0; nt < 8; nt++) {
                const long col = n0 + wx * 64 + nt * 8 + (lane & 3) * 2;
                const float v0 = acc[mt][nt][half * 2 + 0];
                const float v1 = acc[mt][nt][half * 2 + 1];
                if (SPLITOUT) {
                    f16 h0, l0, h1, l1;
                    f16split(v0, h0, l0);
                    f16split(v1, h1, l1);
                    __half2 hv(h0, h1), lv(l0, l1);
                    *(uint32_t*)(Oh + z * cB + row * ldc + col) = *(uint32_t*)&hv;
                    *(uint32_t*)(Ol + z * cB + row * ldc + col) = *(uint32_t*)&lv;
                } else {
                    *(float2*)(C + z * cB + row * ldc + col) = make_float2(v0, v1);
                }
            }
        }
    }
}

// ---------------------------------------------------------------------------
// fp16 GEMM7: out[t,d](b) = sum_s w[t,s] * src[s,d]   (A=w single NT,
// B=src hi/lo via ldsm.trans). CTA 128x128, 4 warps (2x2, 64x64), 2 CTAs/SM.
// ---------------------------------------------------------------------------
#define F16_AT    8192          // w tile 128x64B
#define F16_BT    8192          // one src TR half 32x256B
#define F16_STAGE 24576
#define F16_SM    (3 * F16_STAGE)

__global__ __launch_bounds__(128, 2) void mma_gemm_wf16(
    const f16* __restrict__ W, const f16* __restrict__ Bh, const f16* __restrict__ Bl,
    float* __restrict__ C,
    long lda, long ldb, long ldc, long aB, long bB, long cB)
{
    extern __shared__ char smem[];
    const uint32_t sb = smem_u32(smem);
    const int tid = threadIdx.x;
    const int lane = tid & 31, wid = tid >> 5;
    const int wy = wid >> 1, wx = wid & 1;        // 2x2 warps, 64x64 tiles
    const long m0 = (long)blockIdx.y * 128;
    const long n0 = (long)blockIdx.x * 128;
    const long z  = blockIdx.z;

    const f16* pA  = W  + z * aB + m0 * lda;
    const f16* pBh = Bh + z * bB + n0;
    const f16* pBl = Bl + z * bB + n0;

    float acc[4][8][4] = {};

    auto LOAD = [&](uint32_t st, int chunk) {
        const long k0 = (long)chunk * 32;
        load_nt(st,                   pA + k0,        lda * 2, tid);
        load_tr(st + F16_AT,          pBh + k0 * ldb, ldb * 2, tid);
        load_tr(st + F16_AT + F16_BT, pBl + k0 * ldb, ldb * 2, tid);
    };

    const int hi4 = lane >> 4;
    const uint32_t aRowB = (uint32_t)(wy * 64 + (lane & 15)) * 64;
    const int sA = ((lane & 15) >> 1) & 3;
    const int bSel = (lane >> 3) & 1;
    const uint32_t trRowB = (uint32_t)((lane & 7) + bSel * 8) * 256;
    uint32_t trC[4];
    #pragma unroll
    for (int p = 0; p < 4; p++)
        trC[p] = (uint32_t)((wx * 8 + p * 2 + hi4) ^ (lane & 7)) * 16;

    LOAD(sb, 0); CP_COMMIT();
    LOAD(sb + F16_STAGE, 1); CP_COMMIT();

    const uint32_t sEnd = sb + 3 * F16_STAGE;
    uint32_t stCur = sb;
    uint32_t stLd  = sb + 2 * F16_STAGE;

    const int NC = 32;
    for (int c = 0; c < NC; c++) {
        CP_WAIT1();
        __syncthreads();

        // ---- k16 = 0 fragment loads ----
        uint32_t bh[16], bl[16];
        #pragma unroll
        for (int p = 0; p < 4; p++) {
            ldsm4t(&bh[p * 4], stCur + F16_AT + trRowB + trC[p]);
            ldsm4t(&bl[p * 4], stCur + F16_AT + F16_BT + trRowB + trC[p]);
        }
        const uint32_t aOff0 = (uint32_t)(hi4 ^ sA) * 16;
        uint32_t a0[4];
        ldsm4(a0, stCur + aRowB + aOff0);

        // ---- first MMA burst ----
        #pragma unroll
        for (int nt = 0; nt < 8; nt++) {
            mma_f16(acc[0][nt], a0, &bh[nt * 2]);
            mma_f16(acc[0][nt], a0, &bl[nt * 2]);
        }

        // ---- prefetch (issue hides under queued MMAs) ----
        if (c + 2 < NC) LOAD(stLd, c + 2);
        CP_COMMIT();

        #pragma unroll
        for (int mt = 1; mt < 4; mt++) {
            uint32_t a[4];
            ldsm4(a, stCur + aRowB + (uint32_t)mt * 16 * 64 + aOff0);
            #pragma unroll
            for (int nt = 0; nt < 8; nt++) {
                mma_f16(acc[mt][nt], a, &bh[nt * 2]);
                mma_f16(acc[mt][nt], a, &bl[nt * 2]);
            }
        }

        // ---- k16 = 1 ----
        {
            const uint32_t rOff = trRowB + 16 * 256;
            #pragma unroll
            for (int p = 0; p < 4; p++) {
                ldsm4t(&bh[p * 4], stCur + F16_AT + rOff + trC[p]);
                ldsm4t(&bl[p * 4], stCur + F16_AT + F16_BT + rOff + trC[p]);
            }
        }
        const uint32_t aOff1 = (uint32_t)((2 + hi4) ^ sA) * 16;
        #pragma unroll
        for (int mt = 0; mt < 4; mt++) {
            uint32_t a[4];
            ldsm4(a, stCur + aRowB + (uint32_t)mt * 16 * 64 + aOff1);
            #pragma unroll
            for (int nt = 0; nt < 8; nt++) {
                mma_f16(acc[mt][nt], a, &bh[nt * 2]);
                mma_f16(acc[mt][nt], a, &bl[nt * 2]);
            }
        }

        stCur += F16_STAGE; if (stCur == sEnd) stCur = sb;
        stLd  += F16_STAGE; if (stLd  == sEnd) stLd  = sb;
    }

    #pragma unroll
    for (int mt = 0; mt < 4; mt++) {
        #pragma unroll
        for (int half = 0; half < 2; half++) {
            const long row = m0 + wy * 64 + mt * 16 + (lane >> 2) + half * 8;
            #pragma unroll
            for (int nt = 0; nt < 8; nt++) {
                const long col = n0 + wx * 64 + nt * 8 + (lane & 3) * 2;
                *(float2*)(C + z * cB + row * ldc + col) =
                    make_float2(acc[mt][nt][half * 2], acc[mt][nt][half * 2 + 1]);
            }
        }
    }
}

// ---------------------------------------------------------------------------
// Merged aux kernel: blocks [0,256) = tn_partial (split-K Mt),
// [256, 256+16384) = src fp16 split, rest = tgt fp16 split.
// ---------------------------------------------------------------------------
#define SRC_BLKS 16384
#define AUX_BLKS (256 + 2 * SRC_BLKS)

__device__ __forceinline__ void split_f16_block(
    const float* __restrict__ x, f16* __restrict__ hi, f16* __restrict__ lo, int blk, int tid)
{
    const size_t base = (size_t)blk * 512 + tid;
    #pragma unroll
    for (int q = 0; q < 2; q++) {
        const size_t i4 = base + q * 256;
        float4 v = ((const float4*)x)[i4];
        float f[4] = {v.x, v.y, v.z, v.w};
        uint32_t hw[2], lw[2];
        #pragma unroll
        for (int p = 0; p < 2; p++) {
            f16 h0, l0, h1, l1;
            f16split(f[2 * p], h0, l0);
            f16split(f[2 * p + 1], h1, l1);
            __half2 hv(h0, h1), lv(l0, l1);
            hw[p] = *(uint32_t*)&hv;
            lw[p] = *(uint32_t*)&lv;
        }
        ((uint2*)hi)[i4] = make_uint2(hw[0], hw[1]);
        ((uint2*)lo)[i4] = make_uint2(lw[0], lw[1]);
    }
}

__global__ __launch_bounds__(256) void mega_aux_kernel(
    const float* __restrict__ src, const float* __restrict__ tgt,
    const float* __restrict__ W1, const float* __restrict__ W2)
{
    __shared__ float As[16][128];
    __shared__ float Bs[16][128];

    const int bx = blockIdx.x;
    const int tid = threadIdx.x;

    if (bx < 256) {
        const int kz = (bx >> 6) * 256;
        const int m0 = ((bx >> 3) & 7) * 128;
        const int n0 = (bx & 7) * 128;
        const int tx = tid & 15, ty = tid >> 4;
        const int r8 = tid >> 5, c4 = (tid & 31) * 4;

        float acc[8][8] = {};

        for (int k0 = kz; k0 < kz + 256; k0 += 16) {
            #pragma unroll
            for (int i = 0; i < 2; i++) {
                const int kr = k0 + r8 + i * 8;
                *(float4*)&As[r8 + i * 8][c4] = *(const float4*)(W2 + (size_t)kr * 1024 + m0 + c4);
                *(float4*)&Bs[r8 + i * 8][c4] = *(const float4*)(W1 + (size_t)kr * 1024 + n0 + c4);
            }
            __syncthreads();
            #pragma unroll
            for (int kk = 0; kk < 16; kk++) {
                float ra[8], rb[8];
                *(float4*)&ra[0] = *(const float4*)&As[kk][ty * 8];
                *(float4*)&ra[4] = *(const float4*)&As[kk][ty * 8 + 4];
                *(float4*)&rb[0] = *(const float4*)&Bs[kk][tx * 8];
                *(float4*)&rb[4] = *(const float4*)&Bs[kk][tx * 8 + 4];
                #pragma unroll
                for (int i = 0; i < 8; i++)
                    #pragma unroll
                    for (int j = 0; j < 8; j++)
                        acc[i][j] = fmaf(ra[i], rb[j], acc[i][j]);
            }
            __syncthreads();
        }

        float* part = g_mtPart[bx >> 6];
        #pragma unroll
        for (int i = 0; i < 8; i++) {
            const size_t base = (size_t)(m0 + ty * 8 + i) * 1024 + n0 + tx * 8;
            *(float4*)(part + base)     = make_float4(acc[i][0], acc[i][1], acc[i][2], acc[i][3]);
            *(float4*)(part + base + 4) = make_float4(acc[i][4], acc[i][5], acc[i][6], acc[i][7]);
        }
    } else if (bx < 256 + SRC_BLKS) {
        split_f16_block(src, g_srcHi, g_srcLo, bx - 256, tid);
    } else {
        split_f16_block(tgt, g_tgtHi, g_tgtLo, bx - 256 - SRC_BLKS, tid);
    }
}

// ---------------------------------------------------------------------------
// Reduce 4 Mt partials (fixed order) and split to fp16 hi/lo.
// ---------------------------------------------------------------------------
__global__ __launch_bounds__(256) void mt_reduce_split_kernel()
{
    const size_t i4 = (size_t)blockIdx.x * 256 + threadIdx.x;
    float4 p0 = ((const float4*)g_mtPart[0])[i4];
    float4 p1 = ((const float4*)g_mtPart[1])[i4];
    float4 p2 = ((const float4*)g_mtPart[2])[i4];
    float4 p3 = ((const float4*)g_mtPart[3])[i4];
    float f[4] = {(p0.x + p1.x) + (p2.x + p3.x),
                  (p0.y + p1.y) + (p2.y + p3.y),
                  (p0.z + p1.z) + (p2.z + p3.z),
                  (p0.w + p1.w) + (p2.w + p3.w)};
    uint32_t hw[2], lw[2];
    #pragma unroll
    for (int p = 0; p < 2; p++) {
        f16 h0, l0, h1, l1;
        f16split(f[2 * p], h0, l0);
        f16split(f[2 * p + 1], h1, l1);
        __half2 hv(h0, h1), lv(l0, l1);
        hw[p] = *(uint32_t*)&hv;
        lw[p] = *(uint32_t*)&lv;
    }
    ((uint2*)g_mtHi)[i4] = make_uint2(hw[0], hw[1]);
    ((uint2*)g_mtLo)[i4] = make_uint2(lw[0], lw[1]);
}

// ---------------------------------------------------------------------------
// Softmax over contiguous rows of 1024; writes fp16 weights.
// ---------------------------------------------------------------------------
__global__ __launch_bounds__(256) void softmax_f16_kernel(const float* __restrict__ sc)
{
    const size_t row = blockIdx.x;
    const float4* p = (const float4*)(sc + row * 1024);
    const int tid = threadIdx.x;
    __shared__ float sh[8];

    float4 v = p[tid];

    float m = fmaxf(fmaxf(v.x, v.y), fmaxf(v.z, v.w));
    #pragma unroll
    for (int o = 16; o; o >>= 1) m = fmaxf(m, __shfl_xor_sync(0xffffffffu, m, o));
    if ((tid & 31) == 0) sh[tid >> 5] = m;
    __syncthreads();
    m = sh[0];
    #pragma unroll
    for (int i = 1; i < 8; i++) m = fmaxf(m, sh[i]);
    __syncthreads();

    v.x = __expf(v.x - m); v.y = __expf(v.y - m);
    v.z = __expf(v.z - m); v.w = __expf(v.w - m);
    float s = v.x + v.y + v.z + v.w;
    #pragma unroll
    for (int o = 16; o; o >>= 1) s += __shfl_xor_sync(0xffffffffu, s, o);
    if ((tid & 31) == 0) sh[tid >> 5] = s;
    __syncthreads();
    s = sh[0] + sh[1] + sh[2] + sh[3] + sh[4] + sh[5] + sh[6] + sh[7];
    const float inv = 1.0f / s;

    __half2 w01(__float2half_rn(v.x * inv), __float2half_rn(v.y * inv));
    __half2 w23(__float2half_rn(v.z * inv), __float2half_rn(v.w * inv));
    ((uint2*)(g_wF16 + row * 1024))[tid] = make_uint2(*(uint32_t*)&w01, *(uint32_t*)&w23);
}

// ---------------------------------------------------------------------------
// Host
// ---------------------------------------------------------------------------
extern "C" void kernel_launch(void* const* d_in, const int* in_sizes, int n_in,
                              void* d_out, int out_size)
{
    const float* src = (const float*)d_in[0];  // (S,B,D)
    const float* tgt = (const float*)d_in[1];  // (T,B,D)
    const float* W1  = (const float*)d_in[2];  // (A,D)
    const float* W2  = (const float*)d_in[3];  // (A,D)
    float* out = (float*)d_out;                // (T,B,D)

    void *srcHi, *srcLo, *tgtHi, *tgtLo, *mtHi, *mtLo, *uHi, *uLo, *sc, *wF16;
    cudaGetSymbolAddress(&srcHi, g_srcHi); cudaGetSymbolAddress(&srcLo, g_srcLo);
    cudaGetSymbolAddress(&tgtHi, g_tgtHi); cudaGetSymbolAddress(&tgtLo, g_tgtLo);
    cudaGetSymbolAddress(&mtHi, g_mtHi);   cudaGetSymbolAddress(&mtLo, g_mtLo);
    cudaGetSymbolAddress(&uHi, g_uHi);     cudaGetSymbolAddress(&uLo, g_uLo);
    cudaGetSymbolAddress(&sc, g_sc);       cudaGetSymbolAddress(&wF16, g_wF16);

    cudaFuncSetAttribute(mma_gemm<true>,  cudaFuncAttributeMaxDynamicSharedMemorySize, SM_TOTAL);
    cudaFuncSetAttribute(mma_gemm<false>, cudaFuncAttributeMaxDynamicSharedMemorySize, SM_TOTAL);
    cudaFuncSetAttribute(mma_gemm_wf16,   cudaFuncAttributeMaxDynamicSharedMemorySize, F16_SM);

    // 1. merged aux: tn_partial + src split + tgt split
    mega_aux_kernel<<<AUX_BLKS, 256>>>(src, tgt, W1, W2);
    // 2. Mt reduce + fp16 split
    mt_reduce_split_kernel<<<(A_ * D_ / 4) / 256, 256>>>();

    // 3. u[(s,b), e] = sum_d src * Mt   (fp16x3 NT, M=32768, split output)
    mma_gemm<true><<<dim3(8, 256, 1), 128, SM_TOTAL>>>(
        (const f16*)srcHi, (const f16*)srcLo, (const f16*)mtHi, (const f16*)mtLo,
        nullptr, (f16*)uHi, (f16*)uLo,
        1024, 1024, 1024, 0, 0, 0);

    // 4. scores[b,t,s] = sum_e tgt * u   (fp16x3 NT batched over b)
    mma_gemm<false><<<dim3(8, 8, 32), 128, SM_TOTAL>>>(
        (const f16*)tgtHi, (const f16*)tgtLo, (const f16*)uHi, (const f16*)uLo,
        (float*)sc, nullptr, nullptr,
        32768, 32768, 1024, 1024, 1024, (long)1024 * 1024);

    // 5. softmax over s -> fp16 weights
    softmax_f16_kernel<<<B_ * T_, 256>>>((const float*)sc);

    // 6. out[t,b,d] = sum_s w[b,t,s] * src[s,b,d]   (fp16 2-MMA path)
    mma_gemm_wf16<<<dim3(8, 8, 32), 128, F16_SM>>>(
        (const f16*)wF16, (const f16*)srcHi, (const f16*)srcLo, out,
        1024, 32768, 32768, (long)1024 * 1024, 1024, 1024);
}

// round 17
// speedup vs baseline: 1.0333x; 1.0333x over previous
#include <cuda_runtime.h>
#include <cuda_fp16.h>
#include <cstdint>

typedef __half f16;

#define S_ 1024
#define T_ 1024
#define B_ 32
#define D_ 1024
#define A_ 1024

// ---------------------------------------------------------------------------
// Scratch (device globals; allocation is forbidden)
// ---------------------------------------------------------------------------
__device__ __align__(16) f16  g_srcHi[(size_t)S_ * B_ * D_];   // (S,B,D) fp16 split
__device__ __align__(16) f16  g_srcLo[(size_t)S_ * B_ * D_];
__device__ __align__(16) f16  g_tgtHi[(size_t)T_ * B_ * D_];   // (T,B,D)
__device__ __align__(16) f16  g_tgtLo[(size_t)T_ * B_ * D_];
__device__ __align__(16) f16  g_mtHi[(size_t)A_ * D_];         // Mt[e,d]
__device__ __align__(16) f16  g_mtLo[(size_t)A_ * D_];
__device__ __align__(16) float g_mtPart[4][(size_t)A_ * D_];   // split-K partials
__device__ __align__(16) f16  g_uHi[(size_t)S_ * B_ * A_];     // (S,B,A)
__device__ __align__(16) f16  g_uLo[(size_t)S_ * B_ * A_];
__device__ __align__(16) float g_sc[(size_t)B_ * T_ * S_];     // (B,T,S) scores
__device__ __align__(16) f16  g_wF16[(size_t)B_ * T_ * S_];    // softmax weights fp16

// ---------------------------------------------------------------------------
// Primitives (sm_80-level PTX)
// ---------------------------------------------------------------------------
__device__ __forceinline__ uint32_t smem_u32(const void* p) {
    uint32_t a;
    asm("{ .reg .u64 t; cvta.to.shared.u64 t, %1; cvt.u32.u64 %0, t; }" : "=r"(a) : "l"(p));
    return a;
}

__device__ __forceinline__ void cpa16(uint32_t s, const void* g) {
    asm volatile("cp.async.cg.shared.global [%0], [%1], 16;" :: "r"(s), "l"(g));
}
#define CP_COMMIT() asm volatile("cp.async.commit_group;" ::: "memory")
#define CP_WAIT1()  asm volatile("cp.async.wait_group 1;" ::: "memory")

__device__ __forceinline__ void ldsm4(uint32_t* r, uint32_t a) {
    asm volatile("ldmatrix.sync.aligned.m8n8.x4.shared.b16 {%0,%1,%2,%3}, [%4];"
                 : "=r"(r[0]), "=r"(r[1]), "=r"(r[2]), "=r"(r[3]) : "r"(a));
}
__device__ __forceinline__ void ldsm4t(uint32_t* r, uint32_t a) {
    asm volatile("ldmatrix.sync.aligned.m8n8.x4.trans.shared.b16 {%0,%1,%2,%3}, [%4];"
                 : "=r"(r[0]), "=r"(r[1]), "=r"(r[2]), "=r"(r[3]) : "r"(a));
}
__device__ __forceinline__ void mma_f16(float* c, const uint32_t* a, const uint32_t* b) {
    asm volatile("mma.sync.aligned.m16n8k16.row.col.f32.f16.f16.f32 "
                 "{%0,%1,%2,%3}, {%4,%5,%6,%7}, {%8,%9}, {%0,%1,%2,%3};"
                 : "+f"(c[0]), "+f"(c[1]), "+f"(c[2]), "+f"(c[3])
                 : "r"(a[0]), "r"(a[1]), "r"(a[2]), "r"(a[3]), "r"(b[0]), "r"(b[1]));
}

__device__ __forceinline__ void f16split(float x, f16& h, f16& l) {
    h = __float2half_rn(x);
    l = __float2half_rn(x - __half2float(h));
}

// ---------------------------------------------------------------------------
// Tile loaders (XOR swizzle, no padding), 2B elements, 128-thread CTAs.
// NT tile: 128 rows x 64B (4 iters). TR tile: 32 rows x 256B (4 iters).
// ---------------------------------------------------------------------------
__device__ __forceinline__ void load_nt(uint32_t sbase, const void* g, long ldBytes, int tid) {
    #pragma unroll
    for (int i = 0; i < 4; i++) {
        const int c = tid + i * 128;
        const int row = c >> 2, ch = c & 3;
        const int sw = ch ^ ((row >> 1) & 3);
        cpa16(sbase + row * 64 + sw * 16, (const char*)g + (long)row * ldBytes + ch * 16);
    }
}
__device__ __forceinline__ void load_tr(uint32_t sbase, const void* g, long ldBytes, int tid) {
    #pragma unroll
    for (int i = 0; i < 4; i++) {
        const int c = tid + i * 128;
        const int row = c >> 4, ch = c & 15;
        const int sw = ch ^ (row & 7);
        cpa16(sbase + row * 256 + sw * 16, (const char*)g + (long)row * ldBytes + ch * 16);
    }
}

// ---------------------------------------------------------------------------
// fp16x3-split GEMM (GEMM4/5): C[m,n](z) = sum_k A[m,k]*B[n,k]  (NT)
// CTA 128x128x32, 4 warps (2x2 grid, 64x64 warp tiles), 128 threads,
// 3-stage ring, 2 CTAs/SM. R15-verified order: peel frags -> prefetch -> MMAs.
// acc += Ahi*Bhi + Ahi*Blo + Alo*Bhi
// ---------------------------------------------------------------------------
#define HALF_B   8192           // one tile half: 128 x 64B
#define STAGE_B  32768
#define SM_TOTAL (3 * STAGE_B)  // 98304 per CTA

template <bool SPLITOUT>
__global__ __launch_bounds__(128, 2) void mma_gemm(
    const f16* __restrict__ Ah, const f16* __restrict__ Al,
    const f16* __restrict__ Bh, const f16* __restrict__ Bl,
    float* __restrict__ C, f16* __restrict__ Oh, f16* __restrict__ Ol,
    long lda, long ldb, long ldc, long aB, long bB, long cB)
{
    extern __shared__ char smem[];
    const uint32_t sb = smem_u32(smem);
    const int tid = threadIdx.x;
    const int lane = tid & 31, wid = tid >> 5;
    const int wy = wid >> 1, wx = wid & 1;        // 2x2 warps, 64x64 tiles
    const long m0 = (long)blockIdx.y * 128;
    const long n0 = (long)blockIdx.x * 128;
    const long z  = blockIdx.z;

    const f16* pAh = Ah + z * aB + m0 * lda;
    const f16* pAl = Al + z * aB + m0 * lda;
    const f16* pBh = Bh + z * bB + n0 * ldb;
    const f16* pBl = Bl + z * bB + n0 * ldb;

    float acc[4][8][4] = {};

    auto LOAD = [&](uint32_t st, int chunk) {
        const long k0 = (long)chunk * 32;
        load_nt(st,              pAh + k0, lda * 2, tid);
        load_nt(st + HALF_B,     pAl + k0, lda * 2, tid);
        load_nt(st + 2 * HALF_B, pBh + k0, ldb * 2, tid);
        load_nt(st + 3 * HALF_B, pBl + k0, ldb * 2, tid);
    };

    const int hi4 = lane >> 4;
    const uint32_t aRowB = (uint32_t)(wy * 64 + (lane & 15)) * 64;
    const int sA = ((lane & 15) >> 1) & 3;
    const uint32_t bRowB = (uint32_t)(wx * 64 + (lane & 7) + (hi4 << 3)) * 64;
    const int sB = (((lane & 7) + (hi4 << 3)) >> 1) & 3;
    const int bSel = (lane >> 3) & 1;

    LOAD(sb, 0); CP_COMMIT();
    LOAD(sb + STAGE_B, 1); CP_COMMIT();

    const uint32_t sEnd = sb + 3 * STAGE_B;
    uint32_t stCur = sb;
    uint32_t stLd  = sb + 2 * STAGE_B;

    const int NC = 32;
    for (int c = 0; c < NC; c++) {
        CP_WAIT1();
        __syncthreads();                  // visibility fence + stage-free point

        // ---- k16 = 0 fragment loads (peel) ----
        uint32_t bh[16], bl[16];
        {
            const uint32_t cOff = (uint32_t)(bSel ^ sB) * 16;
            #pragma unroll
            for (int p = 0; p < 4; p++) {
                const uint32_t bd = stCur + 2 * HALF_B + bRowB + (uint32_t)p * 16 * 64 + cOff;
                ldsm4(&bh[p * 4], bd);
                ldsm4(&bl[p * 4], bd + HALF_B);
            }
        }
        const uint32_t aOff0 = (uint32_t)(hi4 ^ sA) * 16;
        uint32_t ah0[4], al0[4];
        {
            const uint32_t ad = stCur + aRowB + aOff0;
            ldsm4(ah0, ad);
            ldsm4(al0, ad + HALF_B);
        }

        // ---- prefetch chunk c+2 (issue hides under in-flight ldsm) ----
        if (c + 2 < NC) LOAD(stLd, c + 2);
        CP_COMMIT();

        // ---- k16 = 0 compute ----
        #pragma unroll
        for (int nt = 0; nt < 8; nt++) {
            mma_f16(acc[0][nt], ah0, &bh[nt * 2]);
            mma_f16(acc[0][nt], ah0, &bl[nt * 2]);
            mma_f16(acc[0][nt], al0, &bh[nt * 2]);
        }
        #pragma unroll
        for (int mt = 1; mt < 4; mt++) {
            uint32_t ah[4], al[4];
            const uint32_t ad = stCur + aRowB + (uint32_t)mt * 16 * 64 + aOff0;
            ldsm4(ah, ad);
            ldsm4(al, ad + HALF_B);
            #pragma unroll
            for (int nt = 0; nt < 8; nt++) {
                mma_f16(acc[mt][nt], ah, &bh[nt * 2]);
                mma_f16(acc[mt][nt], ah, &bl[nt * 2]);
                mma_f16(acc[mt][nt], al, &bh[nt * 2]);
            }
        }

        // ---- k16 = 1 ----
        {
            const uint32_t cOff = (uint32_t)((2 + bSel) ^ sB) * 16;
            #pragma unroll
            for (int p = 0; p < 4; p++) {
                const uint32_t bd = stCur + 2 * HALF_B + bRowB + (uint32_t)p * 16 * 64 + cOff;
                ldsm4(&bh[p * 4], bd);
                ldsm4(&bl[p * 4], bd + HALF_B);
            }
        }
        const uint32_t aOff1 = (uint32_t)((2 + hi4) ^ sA) * 16;
        #pragma unroll
        for (int mt = 0; mt < 4; mt++) {
            uint32_t ah[4], al[4];
            const uint32_t ad = stCur + aRowB + (uint32_t)mt * 16 * 64 + aOff1;
            ldsm4(ah, ad);
            ldsm4(al, ad + HALF_B);
            #pragma unroll
            for (int nt = 0; nt < 8; nt++) {
                mma_f16(acc[mt][nt], ah, &bh[nt * 2]);
                mma_f16(acc[mt][nt], ah, &bl[nt * 2]);
                mma_f16(acc[mt][nt], al, &bh[nt * 2]);
            }
        }

        stCur += STAGE_B; if (stCur == sEnd) stCur = sb;
        stLd  += STAGE_B; if (stLd  == sEnd) stLd  = sb;
    }

    #pragma unroll
    for (int mt = 0; mt < 4; mt++) {
        #pragma unroll
        for (int half = 0; half < 2; half++) {
            const long row = m0 + wy * 64 + mt * 16 + (lane >> 2) + half * 8;
            #pragma unroll
            for (int nt = 0; nt < 8; nt++) {
                const long col = n0 + wx * 64 + nt * 8 + (lane & 3) * 2;
                const float v0 = acc[mt][nt][half * 2 + 0];
                const float v1 = acc[mt][nt][half * 2 + 1];
                if (SPLITOUT) {
                    f16 h0, l0, h1, l1;
                    f16split(v0, h0, l0);
                    f16split(v1, h1, l1);
                    __half2 hv(h0, h1), lv(l0, l1);
                    *(uint32_t*)(Oh + z * cB + row * ldc + col) = *(uint32_t*)&hv;
                    *(uint32_t*)(Ol + z * cB + row * ldc + col) = *(uint32_t*)&lv;
                } else {
                    *(float2*)(C + z * cB + row * ldc + col) = make_float2(v0, v1);
                }
            }
        }
    }
}

// ---------------------------------------------------------------------------
// fp16 GEMM7: out[t,d](b) = sum_s w[t,s] * src[s,d]   (A=w single NT,
// B=src hi/lo via ldsm.trans). CTA 128x128, 4 warps (2x2, 64x64), 2 CTAs/SM.
// ---------------------------------------------------------------------------
#define F16_AT    8192          // w tile 128x64B
#define F16_BT    8192          // one src TR half 32x256B
#define F16_STAGE 24576
#define F16_SM    (3 * F16_STAGE)

__global__ __launch_bounds__(128, 2) void mma_gemm_wf16(
    const f16* __restrict__ W, const f16* __restrict__ Bh, const f16* __restrict__ Bl,
    float* __restrict__ C,
    long lda, long ldb, long ldc, long aB, long bB, long cB)
{
    extern __shared__ char smem[];
    const uint32_t sb = smem_u32(smem);
    const int tid = threadIdx.x;
    const int lane = tid & 31, wid = tid >> 5;
    const int wy = wid >> 1, wx = wid & 1;        // 2x2 warps, 64x64 tiles
    const long m0 = (long)blockIdx.y * 128;
    const long n0 = (long)blockIdx.x * 128;
    const long z  = blockIdx.z;

    const f16* pA  = W  + z * aB + m0 * lda;
    const f16* pBh = Bh + z * bB + n0;
    const f16* pBl = Bl + z * bB + n0;

    float acc[4][8][4] = {};

    auto LOAD = [&](uint32_t st, int chunk) {
        const long k0 = (long)chunk * 32;
        load_nt(st,                   pA + k0,        lda * 2, tid);
        load_tr(st + F16_AT,          pBh + k0 * ldb, ldb * 2, tid);
        load_tr(st + F16_AT + F16_BT, pBl + k0 * ldb, ldb * 2, tid);
    };

    const int hi4 = lane >> 4;
    const uint32_t aRowB = (uint32_t)(wy * 64 + (lane & 15)) * 64;
    const int sA = ((lane & 15) >> 1) & 3;
    const int bSel = (lane >> 3) & 1;
    const uint32_t trRowB = (uint32_t)((lane & 7) + bSel * 8) * 256;
    uint32_t trC[4];
    #pragma unroll
    for (int p = 0; p < 4; p++)
        trC[p] = (uint32_t)((wx * 8 + p * 2 + hi4) ^ (lane & 7)) * 16;

    LOAD(sb, 0); CP_COMMIT();
    LOAD(sb + F16_STAGE, 1); CP_COMMIT();

    const uint32_t sEnd = sb + 3 * F16_STAGE;
    uint32_t stCur = sb;
    uint32_t stLd  = sb + 2 * F16_STAGE;

    const int NC = 32;
    for (int c = 0; c < NC; c++) {
        CP_WAIT1();
        __syncthreads();

        // ---- k16 = 0 fragment loads (peel) ----
        uint32_t bh[16], bl[16];
        #pragma unroll
        for (int p = 0; p < 4; p++) {
            ldsm4t(&bh[p * 4], stCur + F16_AT + trRowB + trC[p]);
            ldsm4t(&bl[p * 4], stCur + F16_AT + F16_BT + trRowB + trC[p]);
        }
        const uint32_t aOff0 = (uint32_t)(hi4 ^ sA) * 16;
        uint32_t a0[4];
        ldsm4(a0, stCur + aRowB + aOff0);

        // ---- prefetch ----
        if (c + 2 < NC) LOAD(stLd, c + 2);
        CP_COMMIT();

        #pragma unroll
        for (int nt = 0; nt < 8; nt++) {
            mma_f16(acc[0][nt], a0, &bh[nt * 2]);
            mma_f16(acc[0][nt], a0, &bl[nt * 2]);
        }
        #pragma unroll
        for (int mt = 1; mt < 4; mt++) {
            uint32_t a[4];
            ldsm4(a, stCur + aRowB + (uint32_t)mt * 16 * 64 + aOff0);
            #pragma unroll
            for (int nt = 0; nt < 8; nt++) {
                mma_f16(acc[mt][nt], a, &bh[nt * 2]);
                mma_f16(acc[mt][nt], a, &bl[nt * 2]);
            }
        }

        // ---- k16 = 1 ----
        {
            const uint32_t rOff = trRowB + 16 * 256;
            #pragma unroll
            for (int p = 0; p < 4; p++) {
                ldsm4t(&bh[p * 4], stCur + F16_AT + rOff + trC[p]);
                ldsm4t(&bl[p * 4], stCur + F16_AT + F16_BT + rOff + trC[p]);
            }
        }
        const uint32_t aOff1 = (uint32_t)((2 + hi4) ^ sA) * 16;
        #pragma unroll
        for (int mt = 0; mt < 4; mt++) {
            uint32_t a[4];
            ldsm4(a, stCur + aRowB + (uint32_t)mt * 16 * 64 + aOff1);
            #pragma unroll
            for (int nt = 0; nt < 8; nt++) {
                mma_f16(acc[mt][nt], a, &bh[nt * 2]);
                mma_f16(acc[mt][nt], a, &bl[nt * 2]);
            }
        }

        stCur += F16_STAGE; if (stCur == sEnd) stCur = sb;
        stLd  += F16_STAGE; if (stLd  == sEnd) stLd  = sb;
    }

    #pragma unroll
    for (int mt = 0; mt < 4; mt++) {
        #pragma unroll
        for (int half = 0; half < 2; half++) {
            const long row = m0 + wy * 64 + mt * 16 + (lane >> 2) + half * 8;
            #pragma unroll
            for (int nt = 0; nt < 8; nt++) {
                const long col = n0 + wx * 64 + nt * 8 + (lane & 3) * 2;
                *(float2*)(C + z * cB + row * ldc + col) =
                    make_float2(acc[mt][nt][half * 2], acc[mt][nt][half * 2 + 1]);
            }
        }
    }
}

// ---------------------------------------------------------------------------
// Merged aux kernel: blocks [0,256) = tn_partial (split-K Mt),
// [256, 256+8192) = src fp16 split (MLP=4), rest = tgt fp16 split.
// ---------------------------------------------------------------------------
#define SRC_BLKS 8192
#define AUX_BLKS (256 + 2 * SRC_BLKS)

__device__ __forceinline__ void split_f16_block(
    const float* __restrict__ x, f16* __restrict__ hi, f16* __restrict__ lo, int blk, int tid)
{
    const size_t base = (size_t)blk * 1024 + tid;
    // 4 independent loads first (MLP = 4), then convert/store
    float4 v[4];
    #pragma unroll
    for (int q = 0; q < 4; q++) v[q] = ((const float4*)x)[base + q * 256];
    #pragma unroll
    for (int q = 0; q < 4; q++) {
        float f[4] = {v[q].x, v[q].y, v[q].z, v[q].w};
        uint32_t hw[2], lw[2];
        #pragma unroll
        for (int p = 0; p < 2; p++) {
            f16 h0, l0, h1, l1;
            f16split(f[2 * p], h0, l0);
            f16split(f[2 * p + 1], h1, l1);
            __half2 hv(h0, h1), lv(l0, l1);
            hw[p] = *(uint32_t*)&hv;
            lw[p] = *(uint32_t*)&lv;
        }
        ((uint2*)hi)[base + q * 256] = make_uint2(hw[0], hw[1]);
        ((uint2*)lo)[base + q * 256] = make_uint2(lw[0], lw[1]);
    }
}

__global__ __launch_bounds__(256) void mega_aux_kernel(
    const float* __restrict__ src, const float* __restrict__ tgt,
    const float* __restrict__ W1, const float* __restrict__ W2)
{
    __shared__ float As[16][128];
    __shared__ float Bs[16][128];

    const int bx = blockIdx.x;
    const int tid = threadIdx.x;

    if (bx < 256) {
        const int kz = (bx >> 6) * 256;
        const int m0 = ((bx >> 3) & 7) * 128;
        const int n0 = (bx & 7) * 128;
        const int tx = tid & 15, ty = tid >> 4;
        const int r8 = tid >> 5, c4 = (tid & 31) * 4;

        float acc[8][8] = {};

        for (int k0 = kz; k0 < kz + 256; k0 += 16) {
            #pragma unroll
            for (int i = 0; i < 2; i++) {
                const int kr = k0 + r8 + i * 8;
                *(float4*)&As[r8 + i * 8][c4] = *(const float4*)(W2 + (size_t)kr * 1024 + m0 + c4);
                *(float4*)&Bs[r8 + i * 8][c4] = *(const float4*)(W1 + (size_t)kr * 1024 + n0 + c4);
            }
            __syncthreads();
            #pragma unroll
            for (int kk = 0; kk < 16; kk++) {
                float ra[8], rb[8];
                *(float4*)&ra[0] = *(const float4*)&As[kk][ty * 8];
                *(float4*)&ra[4] = *(const float4*)&As[kk][ty * 8 + 4];
                *(float4*)&rb[0] = *(const float4*)&Bs[kk][tx * 8];
                *(float4*)&rb[4] = *(const float4*)&Bs[kk][tx * 8 + 4];
                #pragma unroll
                for (int i = 0; i < 8; i++)
                    #pragma unroll
                    for (int j = 0; j < 8; j++)
                        acc[i][j] = fmaf(ra[i], rb[j], acc[i][j]);
            }
            __syncthreads();
        }

        float* part = g_mtPart[bx >> 6];
        #pragma unroll
        for (int i = 0; i < 8; i++) {
            const size_t base = (size_t)(m0 + ty * 8 + i) * 1024 + n0 + tx * 8;
            *(float4*)(part + base)     = make_float4(acc[i][0], acc[i][1], acc[i][2], acc[i][3]);
            *(float4*)(part + base + 4) = make_float4(acc[i][4], acc[i][5], acc[i][6], acc[i][7]);
        }
    } else if (bx < 256 + SRC_BLKS) {
        split_f16_block(src, g_srcHi, g_srcLo, bx - 256, tid);
    } else {
        split_f16_block(tgt, g_tgtHi, g_tgtLo, bx - 256 - SRC_BLKS, tid);
    }
}

// ---------------------------------------------------------------------------
// Reduce 4 Mt partials (fixed order) and split to fp16 hi/lo.
// ---------------------------------------------------------------------------
__global__ __launch_bounds__(256) void mt_reduce_split_kernel()
{
    const size_t i4 = (size_t)blockIdx.x * 256 + threadIdx.x;
    float4 p0 = ((const float4*)g_mtPart[0])[i4];
    float4 p1 = ((const float4*)g_mtPart[1])[i4];
    float4 p2 = ((const float4*)g_mtPart[2])[i4];
    float4 p3 = ((const float4*)g_mtPart[3])[i4];
    float f[4] = {(p0.x + p1.x) + (p2.x + p3.x),
                  (p0.y + p1.y) + (p2.y + p3.y),
                  (p0.z + p1.z) + (p2.z + p3.z),
                  (p0.w + p1.w) + (p2.w + p3.w)};
    uint32_t hw[2], lw[2];
    #pragma unroll
    for (int p = 0; p < 2; p++) {
        f16 h0, l0, h1, l1;
        f16split(f[2 * p], h0, l0);
        f16split(f[2 * p + 1], h1, l1);
        __half2 hv(h0, h1), lv(l0, l1);
        hw[p] = *(uint32_t*)&hv;
        lw[p] = *(uint32_t*)&lv;
    }
    ((uint2*)g_mtHi)[i4] = make_uint2(hw[0], hw[1]);
    ((uint2*)g_mtLo)[i4] = make_uint2(lw[0], lw[1]);
}

// ---------------------------------------------------------------------------
// Softmax over contiguous rows of 1024; writes fp16 weights.
// ---------------------------------------------------------------------------
__global__ __launch_bounds__(256) void softmax_f16_kernel(const float* __restrict__ sc)
{
    const size_t row = blockIdx.x;
    const float4* p = (const float4*)(sc + row * 1024);
    const int tid = threadIdx.x;
    __shared__ float sh[8];

    float4 v = p[tid];

    float m = fmaxf(fmaxf(v.x, v.y), fmaxf(v.z, v.w));
    #pragma unroll
    for (int o = 16; o; o >>= 1) m = fmaxf(m, __shfl_xor_sync(0xffffffffu, m, o));
    if ((tid & 31) == 0) sh[tid >> 5] = m;
    __syncthreads();
    m = sh[0];
    #pragma unroll
    for (int i = 1; i < 8; i++) m = fmaxf(m, sh[i]);
    __syncthreads();

    v.x = __expf(v.x - m); v.y = __expf(v.y - m);
    v.z = __expf(v.z - m); v.w = __expf(v.w - m);
    float s = v.x + v.y + v.z + v.w;
    #pragma unroll
    for (int o = 16; o; o >>= 1) s += __shfl_xor_sync(0xffffffffu, s, o);
    if ((tid & 31) == 0) sh[tid >> 5] = s;
    __syncthreads();
    s = sh[0] + sh[1] + sh[2] + sh[3] + sh[4] + sh[5] + sh[6] + sh[7];
    const float inv = 1.0f / s;

    __half2 w01(__float2half_rn(v.x * inv), __float2half_rn(v.y * inv));
    __half2 w23(__float2half_rn(v.z * inv), __float2half_rn(v.w * inv));
    ((uint2*)(g_wF16 + row * 1024))[tid] = make_uint2(*(uint32_t*)&w01, *(uint32_t*)&w23);
}

// ---------------------------------------------------------------------------
// Host
// ---------------------------------------------------------------------------
extern "C" void kernel_launch(void* const* d_in, const int* in_sizes, int n_in,
                              void* d_out, int out_size)
{
    const float* src = (const float*)d_in[0];  // (S,B,D)
    const float* tgt = (const float*)d_in[1];  // (T,B,D)
    const float* W1  = (const float*)d_in[2];  // (A,D)
    const float* W2  = (const float*)d_in[3];  // (A,D)
    float* out = (float*)d_out;                // (T,B,D)

    void *srcHi, *srcLo, *tgtHi, *tgtLo, *mtHi, *mtLo, *uHi, *uLo, *sc, *wF16;
    cudaGetSymbolAddress(&srcHi, g_srcHi); cudaGetSymbolAddress(&srcLo, g_srcLo);
    cudaGetSymbolAddress(&tgtHi, g_tgtHi); cudaGetSymbolAddress(&tgtLo, g_tgtLo);
    cudaGetSymbolAddress(&mtHi, g_mtHi);   cudaGetSymbolAddress(&mtLo, g_mtLo);
    cudaGetSymbolAddress(&uHi, g_uHi);     cudaGetSymbolAddress(&uLo, g_uLo);
    cudaGetSymbolAddress(&sc, g_sc);       cudaGetSymbolAddress(&wF16, g_wF16);

    cudaFuncSetAttribute(mma_gemm<true>,  cudaFuncAttributeMaxDynamicSharedMemorySize, SM_TOTAL);
    cudaFuncSetAttribute(mma_gemm<false>, cudaFuncAttributeMaxDynamicSharedMemorySize, SM_TOTAL);
    cudaFuncSetAttribute(mma_gemm_wf16,   cudaFuncAttributeMaxDynamicSharedMemorySize, F16_SM);

    // 1. merged aux: tn_partial + src split + tgt split
    mega_aux_kernel<<<AUX_BLKS, 256>>>(src, tgt, W1, W2);
    // 2. Mt reduce + fp16 split
    mt_reduce_split_kernel<<<(A_ * D_ / 4) / 256, 256>>>();

    // 3. u[(s,b), e] = sum_d src * Mt   (fp16x3 NT, M=32768, split output)
    mma_gemm<true><<<dim3(8, 256, 1), 128, SM_TOTAL>>>(
        (const f16*)srcHi, (const f16*)srcLo, (const f16*)mtHi, (const f16*)mtLo,
        nullptr, (f16*)uHi, (f16*)uLo,
        1024, 1024, 1024, 0, 0, 0);

    // 4. scores[b,t,s] = sum_e tgt * u   (fp16x3 NT batched over b)
    mma_gemm<false><<<dim3(8, 8, 32), 128, SM_TOTAL>>>(
        (const f16*)tgtHi, (const f16*)tgtLo, (const f16*)uHi, (const f16*)uLo,
        (float*)sc, nullptr, nullptr,
        32768, 32768, 1024, 1024, 1024, (long)1024 * 1024);

    // 5. softmax over s -> fp16 weights
    softmax_f16_kernel<<<B_ * T_, 256>>>((const float*)sc);

    // 6. out[t,b,d] = sum_s w[b,t,s] * src[s,b,d]   (fp16 2-MMA path)
    mma_gemm_wf16<<<dim3(8, 8, 32), 128, F16_SM>>>(
        (const f16*)wF16, (const f16*)srcHi, (const f16*)srcLo, out,
        1024, 32768, 32768, (long)1024 * 1024, 1024, 1024);
}